// round 14
// baseline (speedup 1.0000x reference)
#include <cuda_runtime.h>
#include <cuda_bf16.h>
#include <float.h>

// BinsChamferLoss (R14: edge-LUT => no down-walk, ~0-iteration up-walk).
// sum over (b,p) of min_t | center(b,p) - target(b,t) |, targets masked to 0 below 0.001.
//
// k_prep (B blocks): sort centers; build 4096-cell EDGE LUT where
//   lut[k] = min{ j : cell(c_j) >= k }  (= lower_bound of cell k's left edge).
// For any t with cell(t) = k:  lut[k] <= lower_bound(t)  (all j < lut[k] have
// cell(c_j) < k <= cell(t) => c_j < t), so the search is lut[k] + short up-walk.
//
// k_main (75 x B, 256 thr, 1 float4/thr): target LDG first (hidden behind
// prologue), scatter into pred/succ slot words, REDG flush, finisher reduce.
//
// Slot word: w[i].lo = maxBelow enc for center i   (enc = bits(t)+1; 0 = none)
//            w[i].hi = minAbove enc for center i-1 (enc = ~bits(t);  0 = none)

#define MAXB 32
#define P_BINS 256
#define MIN_DEPTH 0.001f
#define LUTN 4096
#define NW (P_BINS + 1)
#define TPB 256

__device__ float              g_centers[MAXB * P_BINS];
__device__ unsigned short     g_lut[MAXB * LUTN];
__device__ float              g_cminw[MAXB * 2];      // {cmin, invw}
__device__ unsigned long long g_W[MAXB * NW];         // zero-init = "none"
__device__ float              g_batchSum[MAXB];
__device__ unsigned int       g_cnt[MAXB];
__device__ unsigned int       g_done;

__device__ __forceinline__ unsigned int atom_add_acqrel(unsigned int* p, unsigned int v)
{
    unsigned int old;
    asm volatile("atom.acq_rel.gpu.global.add.u32 %0, [%1], %2;"
                 : "=r"(old) : "l"(p), "r"(v) : "memory");
    return old;
}
__device__ __forceinline__ void red_max_relaxed(unsigned int* p, unsigned int v)
{
    asm volatile("red.relaxed.gpu.global.max.u32 [%0], %1;" :: "l"(p), "r"(v) : "memory");
}

// ---------------- Kernel 1: sort centers + edge LUT, once per batch -------
__global__ void __launch_bounds__(P_BINS)
k_prep(const float* __restrict__ bins)
{
    const int b   = blockIdx.x;
    const int tid = threadIdx.x;

    __shared__ float sC[P_BINS];

    float v;
    {
        const float* bb = bins + b * (P_BINS + 1);
        v = 0.5f * (bb[tid] + bb[tid + 1]);
    }

#pragma unroll
    for (int k = 2; k <= P_BINS; k <<= 1) {
#pragma unroll
        for (int j = k >> 1; j >= 1; j >>= 1) {
            bool up = ((tid & k) == 0);
            float other;
            if (j >= 32) {
                __syncthreads();
                sC[tid] = v;
                __syncthreads();
                other = sC[tid ^ j];
            } else {
                other = __shfl_xor_sync(0xffffffffu, v, j);
            }
            bool lower = ((tid & j) == 0);
            v = (lower == up) ? fminf(v, other) : fmaxf(v, other);
        }
    }
    __syncthreads();
    sC[tid] = v;
    g_centers[b * P_BINS + tid] = v;
    __syncthreads();

    const float cmin = sC[0];
    const float cmax = sC[P_BINS - 1];
    const float span = cmax - cmin;
    const float invw = (span > 0.0f) ? ((float)LUTN / span) : 0.0f;
    if (tid == 0) { g_cminw[b * 2] = cmin; g_cminw[b * 2 + 1] = invw; }

    // Edge LUT: thread j writes value j to cells (cell(c_{j-1}), cell(c_j)];
    // thread 0 starts at cell 0; thread 255 fills the tail with P_BINS.
    {
        int cj = min(LUTN - 1, max(0, (int)((sC[tid] - cmin) * invw)));
        int cp = (tid == 0) ? -1
               : min(LUTN - 1, max(0, (int)((sC[tid - 1] - cmin) * invw)));
        for (int k = cp + 1; k <= cj; ++k) g_lut[b * LUTN + k] = (unsigned short)tid;
        if (tid == P_BINS - 1)
            for (int k = cj + 1; k < LUTN; ++k) g_lut[b * LUTN + k] = (unsigned short)P_BINS;
    }
}

// ---------------- Kernel 2: scatter + reduce ------------------------------
__global__ void __launch_bounds__(TPB)
k_main(const float* __restrict__ depth, int M, int B, float* __restrict__ out)
{
    const int b    = blockIdx.y;
    const int tid  = threadIdx.x;
    const int lane = tid & 31;
    const int warp = tid >> 5;

    __shared__ float              sC[P_BINS];
    __shared__ unsigned long long sW[NW];
    __shared__ unsigned int       sLUT[LUTN / 2];
    __shared__ unsigned int       wA[8], wS[8];
    __shared__ float              wsum[8];
    __shared__ int                sFinisher;

    // ---- Issue the target load FIRST (DRAM latency hidden by prologue) ----
    const int M4 = M >> 2;                                  // M % 4 == 0
    const int i = blockIdx.x * TPB + tid;
    float4 vv = make_float4(0.f, 0.f, 0.f, 0.f);
    bool have = (i < M4);
    if (have) vv = ((const float4*)(depth + (long long)b * M))[i];

    // ---- Prologue: load published tables (coalesced) ----
    sC[tid] = g_centers[b * P_BINS + tid];
    {
        const unsigned int* lsrc = (const unsigned int*)(g_lut + b * LUTN);
        unsigned int* ldst = sLUT;
#pragma unroll
        for (int r = 0; r < (LUTN / 2) / TPB; ++r)
            ldst[tid + r * TPB] = lsrc[tid + r * TPB];
    }
    sW[tid] = 0ull;
    if (tid == 0) sW[P_BINS] = 0ull;
    const float cmin = g_cminw[b * 2];
    const float invw = g_cminw[b * 2 + 1];
    __syncthreads();

    const unsigned short* lut16 = (const unsigned short*)sLUT;

    // ---- Scatter: one float4 per thread; edge-LUT + up-walk only ----
    if (have) {
        float t[4] = {vv.x, vv.y, vv.z, vv.w};
        int   base[4];
        unsigned int tb[4];

        // Stage 1: mask + 4 independent LUT loads
#pragma unroll
        for (int q = 0; q < 4; ++q) {
            t[q] = (t[q] >= MIN_DEPTH) ? t[q] : 0.0f;
            tb[q] = __float_as_uint(t[q]);
            int k = min(LUTN - 1, max(0, (int)((t[q] - cmin) * invw)));
            base[q] = (int)lut16[k];
        }

        // Stage 2: up-walk (usually 0 iterations) + record
#pragma unroll
        for (int q = 0; q < 4; ++q) {
            float tq = t[q];
            int bs = base[q];
            float cur = 0.0f;
            while (bs < P_BINS) {
                cur = sC[bs];
                if (cur < tq) ++bs; else break;
            }
            // bs == lower_bound(sC, tq)

            unsigned long long w = sW[bs];          // one LDS.64 filter read
            unsigned int encA = tb[q] + 1u;
            if (bs < P_BINS && (unsigned int)w < encA)
                atomicMax((unsigned int*)&sW[bs], encA);

            int ub = bs;
            if (bs < P_BINS && cur == tq) {         // ties ~never; exactness kept
                ++ub;
                while (ub < P_BINS && sC[ub] == tq) ++ub;
            }
            unsigned int encS = ~tb[q];
            if (ub > 0) {
                unsigned int hi = (ub == bs) ? (unsigned int)(w >> 32)
                                             : ((unsigned int*)&sW[ub])[1];
                if (hi < encS)
                    atomicMax(((unsigned int*)&sW[ub]) + 1, encS);
            }
        }
    }
    __syncthreads();

    // ---- Flush: no-return REDG (ordered by the acq_rel arrive below) ----
    {
#pragma unroll
        for (int rep = 0; rep < 2; ++rep) {
            int idx = (rep == 0) ? tid : P_BINS;
            if (rep == 1 && tid != 0) break;
            unsigned long long vw = sW[idx];
            if (vw) {
                unsigned int* p = (unsigned int*)&g_W[b * NW + idx];
                unsigned int lo = (unsigned int)vw, hi = (unsigned int)(vw >> 32);
                if (lo) red_max_relaxed(p, lo);
                if (hi) red_max_relaxed(p + 1, hi);
            }
        }
    }

    // ---- Last block of this batch reduces it (acq_rel arrive) ----
    if (tid == 0) {
        unsigned int old = atom_add_acqrel(&g_cnt[b], 1u);
        sFinisher = (old == (unsigned)(gridDim.x - 1));
    }
    __syncthreads();
    if (!sFinisher) return;

    unsigned long long w0 = g_W[b * NW + tid];
    unsigned long long w1 = g_W[b * NW + tid + 1];
    __syncthreads();                               // reads before resets
    g_W[b * NW + tid] = 0ull;                      // reset for graph replay
    if (tid == 0) { g_W[b * NW + P_BINS] = 0ull; g_cnt[b] = 0u; }

    unsigned int encA = (unsigned int)w0;          // A[tid]
    unsigned int encS = (unsigned int)(w1 >> 32);  // S[tid]

    // prefix-max / suffix-max scans, shuffle-based
    unsigned int pv = encA;
#pragma unroll
    for (int o = 1; o < 32; o <<= 1) {
        unsigned int n = __shfl_up_sync(0xffffffffu, pv, o);
        if (lane >= o) pv = max(pv, n);
    }
    if (lane == 31) wA[warp] = pv;

    unsigned int sv = encS;
#pragma unroll
    for (int o = 1; o < 32; o <<= 1) {
        unsigned int n = __shfl_down_sync(0xffffffffu, sv, o);
        if (lane + o < 32) sv = max(sv, n);
    }
    if (lane == 0) wS[warp] = sv;
    __syncthreads();

    unsigned int offA = 0u, offS = 0u;
    for (int w = 0; w < warp; ++w)     offA = max(offA, wA[w]);
    for (int w = warp + 1; w < 8; ++w) offS = max(offS, wS[w]);
    pv = max(pv, offA);
    sv = max(sv, offS);

    float c   = sC[tid];
    float dLo = pv ? (c - __uint_as_float(pv - 1u)) : FLT_MAX;
    float dHi = sv ? (__uint_as_float(~sv) - c)     : FLT_MAX;
    float d   = fminf(dLo, dHi);

#pragma unroll
    for (int o = 16; o >= 1; o >>= 1) d += __shfl_down_sync(0xffffffffu, d, o);
    if (lane == 0) wsum[warp] = d;
    __syncthreads();

    if (tid == 0) {
        float s = 0.0f;
        for (int w = 0; w < 8; ++w) s += wsum[w];
        g_batchSum[b] = s;

        unsigned int old = atom_add_acqrel(&g_done, 1u);
        if (old == (unsigned)(B - 1)) {
            float tot = 0.0f;
            for (int j = 0; j < B; ++j) tot += g_batchSum[j];
            out[0] = tot;
            g_done = 0u;   // reset for next replay
        }
    }
}

extern "C" void kernel_launch(void* const* d_in, const int* in_sizes, int n_in,
                              void* d_out, int out_size)
{
    int bi = 0, di = 1;
    if (n_in >= 2 && in_sizes[0] > in_sizes[1]) { bi = 1; di = 0; }
    const float* bins  = (const float*)d_in[bi];
    const float* depth = (const float*)d_in[di];

    const int B = in_sizes[bi] / (P_BINS + 1);
    const int M = in_sizes[di] / B;

    const int M4 = M >> 2;
    const int splits = (M4 + TPB - 1) / TPB;   // 75 for 320x240: one float4/thread

    k_prep<<<B, P_BINS>>>(bins);
    dim3 grid(splits, B);
    k_main<<<grid, TPB>>>(depth, M, B, (float*)d_out);
}

// round 15
// speedup vs baseline: 1.0804x; 1.0804x over previous
#include <cuda_runtime.h>
#include <cuda_bf16.h>
#include <float.h>

// BinsChamferLoss (R15: R14's best k_main kept verbatim; k_prep LUT staged in
// smem with coalesced global dump — fixes the R14 prep-tail regression).
//
// k_prep (B blocks): sort centers; build 4096-cell EDGE LUT in smem
//   (init all cells to P_BINS coalesced => tail fill for free; each thread
//    then writes its (cell(c_{j-1}), cell(c_j)] range), dump as uint4.
//   lut[k] = min{ j : cell(c_j) >= k }, so for t in cell k: lut[k] <= lower_bound(t).
//
// k_main (75 x B, 256 thr, 1 float4/thr): target LDG first, edge-LUT + up-walk
// scatter into pred/succ slot words, REDG flush, finisher reduce per batch.
//
// Slot word: w[i].lo = maxBelow enc for center i   (enc = bits(t)+1; 0 = none)
//            w[i].hi = minAbove enc for center i-1 (enc = ~bits(t);  0 = none)

#define MAXB 32
#define P_BINS 256
#define MIN_DEPTH 0.001f
#define LUTN 4096
#define NW (P_BINS + 1)
#define TPB 256

__device__ float              g_centers[MAXB * P_BINS];
__device__ unsigned short     g_lut[MAXB * LUTN];
__device__ float              g_cminw[MAXB * 2];      // {cmin, invw}
__device__ unsigned long long g_W[MAXB * NW];         // zero-init = "none"
__device__ float              g_batchSum[MAXB];
__device__ unsigned int       g_cnt[MAXB];
__device__ unsigned int       g_done;

__device__ __forceinline__ unsigned int atom_add_acqrel(unsigned int* p, unsigned int v)
{
    unsigned int old;
    asm volatile("atom.acq_rel.gpu.global.add.u32 %0, [%1], %2;"
                 : "=r"(old) : "l"(p), "r"(v) : "memory");
    return old;
}
__device__ __forceinline__ void red_max_relaxed(unsigned int* p, unsigned int v)
{
    asm volatile("red.relaxed.gpu.global.max.u32 [%0], %1;" :: "l"(p), "r"(v) : "memory");
}

// ---------------- Kernel 1: sort centers + edge LUT (smem-staged) ---------
__global__ void __launch_bounds__(P_BINS)
k_prep(const float* __restrict__ bins)
{
    const int b   = blockIdx.x;
    const int tid = threadIdx.x;

    __shared__ float          sC[P_BINS];
    __shared__ unsigned short sL[LUTN];

    float v;
    {
        const float* bb = bins + b * (P_BINS + 1);
        v = 0.5f * (bb[tid] + bb[tid + 1]);
    }

    // Init LUT to P_BINS (doubles as the tail fill), coalesced u32 stores.
    {
        unsigned int fill = ((unsigned int)P_BINS << 16) | (unsigned int)P_BINS;
        unsigned int* l32 = (unsigned int*)sL;
#pragma unroll
        for (int r = 0; r < (LUTN / 2) / P_BINS; ++r)
            l32[tid + r * P_BINS] = fill;
    }

#pragma unroll
    for (int k = 2; k <= P_BINS; k <<= 1) {
#pragma unroll
        for (int j = k >> 1; j >= 1; j >>= 1) {
            bool up = ((tid & k) == 0);
            float other;
            if (j >= 32) {
                __syncthreads();
                sC[tid] = v;
                __syncthreads();
                other = sC[tid ^ j];
            } else {
                other = __shfl_xor_sync(0xffffffffu, v, j);
            }
            bool lower = ((tid & j) == 0);
            v = (lower == up) ? fminf(v, other) : fmaxf(v, other);
        }
    }
    __syncthreads();
    sC[tid] = v;
    g_centers[b * P_BINS + tid] = v;
    __syncthreads();

    const float cmin = sC[0];
    const float cmax = sC[P_BINS - 1];
    const float span = cmax - cmin;
    const float invw = (span > 0.0f) ? ((float)LUTN / span) : 0.0f;
    if (tid == 0) { g_cminw[b * 2] = cmin; g_cminw[b * 2 + 1] = invw; }

    // Edge LUT in smem: thread j writes j to cells (cell(c_{j-1}), cell(c_j)].
    {
        int cj = min(LUTN - 1, max(0, (int)((sC[tid] - cmin) * invw)));
        int cp = (tid == 0) ? -1
               : min(LUTN - 1, max(0, (int)((sC[tid - 1] - cmin) * invw)));
        for (int k = cp + 1; k <= cj; ++k) sL[k] = (unsigned short)tid;
    }
    __syncthreads();

    // Coalesced dump: 4096 ushorts = 512 uint4 -> 2 stores/thread.
    {
        const uint4* src = (const uint4*)sL;
        uint4* dst = (uint4*)(g_lut + b * LUTN);
        dst[tid]          = src[tid];
        dst[tid + P_BINS] = src[tid + P_BINS];
    }
}

// ---------------- Kernel 2: scatter + reduce (R14 body, verbatim) ---------
__global__ void __launch_bounds__(TPB)
k_main(const float* __restrict__ depth, int M, int B, float* __restrict__ out)
{
    const int b    = blockIdx.y;
    const int tid  = threadIdx.x;
    const int lane = tid & 31;
    const int warp = tid >> 5;

    __shared__ float              sC[P_BINS];
    __shared__ unsigned long long sW[NW];
    __shared__ unsigned int       sLUT[LUTN / 2];
    __shared__ unsigned int       wA[8], wS[8];
    __shared__ float              wsum[8];
    __shared__ int                sFinisher;

    // ---- Issue the target load FIRST (DRAM latency hidden by prologue) ----
    const int M4 = M >> 2;                                  // M % 4 == 0
    const int i = blockIdx.x * TPB + tid;
    float4 vv = make_float4(0.f, 0.f, 0.f, 0.f);
    bool have = (i < M4);
    if (have) vv = ((const float4*)(depth + (long long)b * M))[i];

    // ---- Prologue: load published tables (coalesced) ----
    sC[tid] = g_centers[b * P_BINS + tid];
    {
        const unsigned int* lsrc = (const unsigned int*)(g_lut + b * LUTN);
        unsigned int* ldst = sLUT;
#pragma unroll
        for (int r = 0; r < (LUTN / 2) / TPB; ++r)
            ldst[tid + r * TPB] = lsrc[tid + r * TPB];
    }
    sW[tid] = 0ull;
    if (tid == 0) sW[P_BINS] = 0ull;
    const float cmin = g_cminw[b * 2];
    const float invw = g_cminw[b * 2 + 1];
    __syncthreads();

    const unsigned short* lut16 = (const unsigned short*)sLUT;

    // ---- Scatter: one float4 per thread; edge-LUT + up-walk only ----
    if (have) {
        float t[4] = {vv.x, vv.y, vv.z, vv.w};
        int   base[4];
        unsigned int tb[4];

#pragma unroll
        for (int q = 0; q < 4; ++q) {
            t[q] = (t[q] >= MIN_DEPTH) ? t[q] : 0.0f;
            tb[q] = __float_as_uint(t[q]);
            int k = min(LUTN - 1, max(0, (int)((t[q] - cmin) * invw)));
            base[q] = (int)lut16[k];
        }

#pragma unroll
        for (int q = 0; q < 4; ++q) {
            float tq = t[q];
            int bs = base[q];
            float cur = 0.0f;
            while (bs < P_BINS) {
                cur = sC[bs];
                if (cur < tq) ++bs; else break;
            }
            // bs == lower_bound(sC, tq)

            unsigned long long w = sW[bs];          // one LDS.64 filter read
            unsigned int encA = tb[q] + 1u;
            if (bs < P_BINS && (unsigned int)w < encA)
                atomicMax((unsigned int*)&sW[bs], encA);

            int ub = bs;
            if (bs < P_BINS && cur == tq) {         // ties ~never; exactness kept
                ++ub;
                while (ub < P_BINS && sC[ub] == tq) ++ub;
            }
            unsigned int encS = ~tb[q];
            if (ub > 0) {
                unsigned int hi = (ub == bs) ? (unsigned int)(w >> 32)
                                             : ((unsigned int*)&sW[ub])[1];
                if (hi < encS)
                    atomicMax(((unsigned int*)&sW[ub]) + 1, encS);
            }
        }
    }
    __syncthreads();

    // ---- Flush: no-return REDG (ordered by the acq_rel arrive below) ----
    {
#pragma unroll
        for (int rep = 0; rep < 2; ++rep) {
            int idx = (rep == 0) ? tid : P_BINS;
            if (rep == 1 && tid != 0) break;
            unsigned long long vw = sW[idx];
            if (vw) {
                unsigned int* p = (unsigned int*)&g_W[b * NW + idx];
                unsigned int lo = (unsigned int)vw, hi = (unsigned int)(vw >> 32);
                if (lo) red_max_relaxed(p, lo);
                if (hi) red_max_relaxed(p + 1, hi);
            }
        }
    }

    // ---- Last block of this batch reduces it (acq_rel arrive) ----
    if (tid == 0) {
        unsigned int old = atom_add_acqrel(&g_cnt[b], 1u);
        sFinisher = (old == (unsigned)(gridDim.x - 1));
    }
    __syncthreads();
    if (!sFinisher) return;

    unsigned long long w0 = g_W[b * NW + tid];
    unsigned long long w1 = g_W[b * NW + tid + 1];
    __syncthreads();                               // reads before resets
    g_W[b * NW + tid] = 0ull;                      // reset for graph replay
    if (tid == 0) { g_W[b * NW + P_BINS] = 0ull; g_cnt[b] = 0u; }

    unsigned int encA = (unsigned int)w0;          // A[tid]
    unsigned int encS = (unsigned int)(w1 >> 32);  // S[tid]

    // prefix-max / suffix-max scans, shuffle-based
    unsigned int pv = encA;
#pragma unroll
    for (int o = 1; o < 32; o <<= 1) {
        unsigned int n = __shfl_up_sync(0xffffffffu, pv, o);
        if (lane >= o) pv = max(pv, n);
    }
    if (lane == 31) wA[warp] = pv;

    unsigned int sv = encS;
#pragma unroll
    for (int o = 1; o < 32; o <<= 1) {
        unsigned int n = __shfl_down_sync(0xffffffffu, sv, o);
        if (lane + o < 32) sv = max(sv, n);
    }
    if (lane == 0) wS[warp] = sv;
    __syncthreads();

    unsigned int offA = 0u, offS = 0u;
    for (int w = 0; w < warp; ++w)     offA = max(offA, wA[w]);
    for (int w = warp + 1; w < 8; ++w) offS = max(offS, wS[w]);
    pv = max(pv, offA);
    sv = max(sv, offS);

    float c   = sC[tid];
    float dLo = pv ? (c - __uint_as_float(pv - 1u)) : FLT_MAX;
    float dHi = sv ? (__uint_as_float(~sv) - c)     : FLT_MAX;
    float d   = fminf(dLo, dHi);

#pragma unroll
    for (int o = 16; o >= 1; o >>= 1) d += __shfl_down_sync(0xffffffffu, d, o);
    if (lane == 0) wsum[warp] = d;
    __syncthreads();

    if (tid == 0) {
        float s = 0.0f;
        for (int w = 0; w < 8; ++w) s += wsum[w];
        g_batchSum[b] = s;

        unsigned int old = atom_add_acqrel(&g_done, 1u);
        if (old == (unsigned)(B - 1)) {
            float tot = 0.0f;
            for (int j = 0; j < B; ++j) tot += g_batchSum[j];
            out[0] = tot;
            g_done = 0u;   // reset for next replay
        }
    }
}

extern "C" void kernel_launch(void* const* d_in, const int* in_sizes, int n_in,
                              void* d_out, int out_size)
{
    int bi = 0, di = 1;
    if (n_in >= 2 && in_sizes[0] > in_sizes[1]) { bi = 1; di = 0; }
    const float* bins  = (const float*)d_in[bi];
    const float* depth = (const float*)d_in[di];

    const int B = in_sizes[bi] / (P_BINS + 1);
    const int M = in_sizes[di] / B;

    const int M4 = M >> 2;
    const int splits = (M4 + TPB - 1) / TPB;   // 75 for 320x240: one float4/thread

    k_prep<<<B, P_BINS>>>(bins);
    dim3 grid(splits, B);
    k_main<<<grid, TPB>>>(depth, M, B, (float*)d_out);
}

// round 16
// speedup vs baseline: 1.2484x; 1.1555x over previous
#include <cuda_runtime.h>
#include <cuda_bf16.h>
#include <float.h>

// BinsChamferLoss (R16: R10's cheap 1024-cell prep + R14's edge-LUT k_main).
// sum over (b,p) of min_t | center(b,p) - target(b,t) |, targets masked to 0 below 0.001.
//
// k_prep (B blocks): sort centers; build 1024-cell EDGE LUT directly in global:
//   lut[k] = min{ j : cell(c_j) >= k }. For t in cell k, lut[k] <= lower_bound(t)
//   (monotone cell map), so k_main needs only a short up-walk (Poisson(0.25)/cell).
//
// k_main (75 x B, 256 thr, 1 float4/thr): target LDG first, edge-LUT + up-walk
// scatter into pred/succ slot words, REDG flush, finisher reduce per batch.
//
// Slot word: w[i].lo = maxBelow enc for center i   (enc = bits(t)+1; 0 = none)
//            w[i].hi = minAbove enc for center i-1 (enc = ~bits(t);  0 = none)

#define MAXB 32
#define P_BINS 256
#define MIN_DEPTH 0.001f
#define LUTN 1024
#define NW (P_BINS + 1)
#define TPB 256

__device__ float              g_centers[MAXB * P_BINS];
__device__ unsigned short     g_lut[MAXB * LUTN];
__device__ float              g_cminw[MAXB * 2];      // {cmin, invw}
__device__ unsigned long long g_W[MAXB * NW];         // zero-init = "none"
__device__ float              g_batchSum[MAXB];
__device__ unsigned int       g_cnt[MAXB];
__device__ unsigned int       g_done;

__device__ __forceinline__ unsigned int atom_add_acqrel(unsigned int* p, unsigned int v)
{
    unsigned int old;
    asm volatile("atom.acq_rel.gpu.global.add.u32 %0, [%1], %2;"
                 : "=r"(old) : "l"(p), "r"(v) : "memory");
    return old;
}
__device__ __forceinline__ void red_max_relaxed(unsigned int* p, unsigned int v)
{
    asm volatile("red.relaxed.gpu.global.max.u32 [%0], %1;" :: "l"(p), "r"(v) : "memory");
}

// ---------------- Kernel 1: sort centers + 1024-cell edge LUT -------------
__global__ void __launch_bounds__(P_BINS)
k_prep(const float* __restrict__ bins)
{
    const int b   = blockIdx.x;
    const int tid = threadIdx.x;

    __shared__ float sC[P_BINS];

    float v;
    {
        const float* bb = bins + b * (P_BINS + 1);
        v = 0.5f * (bb[tid] + bb[tid + 1]);
    }

#pragma unroll
    for (int k = 2; k <= P_BINS; k <<= 1) {
#pragma unroll
        for (int j = k >> 1; j >= 1; j >>= 1) {
            bool up = ((tid & k) == 0);
            float other;
            if (j >= 32) {
                __syncthreads();
                sC[tid] = v;
                __syncthreads();
                other = sC[tid ^ j];
            } else {
                other = __shfl_xor_sync(0xffffffffu, v, j);
            }
            bool lower = ((tid & j) == 0);
            v = (lower == up) ? fminf(v, other) : fmaxf(v, other);
        }
    }
    __syncthreads();
    sC[tid] = v;
    g_centers[b * P_BINS + tid] = v;
    __syncthreads();

    const float cmin = sC[0];
    const float cmax = sC[P_BINS - 1];
    const float span = cmax - cmin;
    const float invw = (span > 0.0f) ? ((float)LUTN / span) : 0.0f;
    if (tid == 0) { g_cminw[b * 2] = cmin; g_cminw[b * 2 + 1] = invw; }

    // Edge LUT: thread j writes j to cells (cell(c_{j-1}), cell(c_j)].
    // cell(c_255) clamps to LUTN-1, so the tail loop is empty in practice.
    {
        int cj = min(LUTN - 1, max(0, (int)((sC[tid] - cmin) * invw)));
        int cp = (tid == 0) ? -1
               : min(LUTN - 1, max(0, (int)((sC[tid - 1] - cmin) * invw)));
        for (int k = cp + 1; k <= cj; ++k) g_lut[b * LUTN + k] = (unsigned short)tid;
        if (tid == P_BINS - 1)
            for (int k = cj + 1; k < LUTN; ++k) g_lut[b * LUTN + k] = (unsigned short)P_BINS;
    }
}

// ---------------- Kernel 2: scatter + reduce (R14 body) -------------------
__global__ void __launch_bounds__(TPB)
k_main(const float* __restrict__ depth, int M, int B, float* __restrict__ out)
{
    const int b    = blockIdx.y;
    const int tid  = threadIdx.x;
    const int lane = tid & 31;
    const int warp = tid >> 5;

    __shared__ float              sC[P_BINS];
    __shared__ unsigned long long sW[NW];
    __shared__ unsigned int       sLUT[LUTN / 2];
    __shared__ unsigned int       wA[8], wS[8];
    __shared__ float              wsum[8];
    __shared__ int                sFinisher;

    // ---- Issue the target load FIRST (DRAM latency hidden by prologue) ----
    const int M4 = M >> 2;                                  // M % 4 == 0
    const int i = blockIdx.x * TPB + tid;
    float4 vv = make_float4(0.f, 0.f, 0.f, 0.f);
    bool have = (i < M4);
    if (have) vv = ((const float4*)(depth + (long long)b * M))[i];

    // ---- Prologue: load published tables (coalesced) ----
    sC[tid] = g_centers[b * P_BINS + tid];
    {
        const unsigned int* lsrc = (const unsigned int*)(g_lut + b * LUTN);
#pragma unroll
        for (int r = 0; r < (LUTN / 2) / TPB; ++r)
            sLUT[tid + r * TPB] = lsrc[tid + r * TPB];
    }
    sW[tid] = 0ull;
    if (tid == 0) sW[P_BINS] = 0ull;
    const float cmin = g_cminw[b * 2];
    const float invw = g_cminw[b * 2 + 1];
    __syncthreads();

    const unsigned short* lut16 = (const unsigned short*)sLUT;

    // ---- Scatter: one float4 per thread; edge-LUT + up-walk only ----
    if (have) {
        float t[4] = {vv.x, vv.y, vv.z, vv.w};
        int   base[4];
        unsigned int tb[4];

#pragma unroll
        for (int q = 0; q < 4; ++q) {
            t[q] = (t[q] >= MIN_DEPTH) ? t[q] : 0.0f;
            tb[q] = __float_as_uint(t[q]);
            int k = min(LUTN - 1, max(0, (int)((t[q] - cmin) * invw)));
            base[q] = (int)lut16[k];
        }

#pragma unroll
        for (int q = 0; q < 4; ++q) {
            float tq = t[q];
            int bs = base[q];
            float cur = 0.0f;
            while (bs < P_BINS) {
                cur = sC[bs];
                if (cur < tq) ++bs; else break;
            }
            // bs == lower_bound(sC, tq)

            unsigned long long w = sW[bs];          // one LDS.64 filter read
            unsigned int encA = tb[q] + 1u;
            if (bs < P_BINS && (unsigned int)w < encA)
                atomicMax((unsigned int*)&sW[bs], encA);

            int ub = bs;
            if (bs < P_BINS && cur == tq) {         // ties ~never; exactness kept
                ++ub;
                while (ub < P_BINS && sC[ub] == tq) ++ub;
            }
            unsigned int encS = ~tb[q];
            if (ub > 0) {
                unsigned int hi = (ub == bs) ? (unsigned int)(w >> 32)
                                             : ((unsigned int*)&sW[ub])[1];
                if (hi < encS)
                    atomicMax(((unsigned int*)&sW[ub]) + 1, encS);
            }
        }
    }
    __syncthreads();

    // ---- Flush: no-return REDG (ordered by the acq_rel arrive below) ----
    {
#pragma unroll
        for (int rep = 0; rep < 2; ++rep) {
            int idx = (rep == 0) ? tid : P_BINS;
            if (rep == 1 && tid != 0) break;
            unsigned long long vw = sW[idx];
            if (vw) {
                unsigned int* p = (unsigned int*)&g_W[b * NW + idx];
                unsigned int lo = (unsigned int)vw, hi = (unsigned int)(vw >> 32);
                if (lo) red_max_relaxed(p, lo);
                if (hi) red_max_relaxed(p + 1, hi);
            }
        }
    }

    // ---- Last block of this batch reduces it (acq_rel arrive) ----
    if (tid == 0) {
        unsigned int old = atom_add_acqrel(&g_cnt[b], 1u);
        sFinisher = (old == (unsigned)(gridDim.x - 1));
    }
    __syncthreads();
    if (!sFinisher) return;

    unsigned long long w0 = g_W[b * NW + tid];
    unsigned long long w1 = g_W[b * NW + tid + 1];
    __syncthreads();                               // reads before resets
    g_W[b * NW + tid] = 0ull;                      // reset for graph replay
    if (tid == 0) { g_W[b * NW + P_BINS] = 0ull; g_cnt[b] = 0u; }

    unsigned int encA = (unsigned int)w0;          // A[tid]
    unsigned int encS = (unsigned int)(w1 >> 32);  // S[tid]

    // prefix-max / suffix-max scans, shuffle-based
    unsigned int pv = encA;
#pragma unroll
    for (int o = 1; o < 32; o <<= 1) {
        unsigned int n = __shfl_up_sync(0xffffffffu, pv, o);
        if (lane >= o) pv = max(pv, n);
    }
    if (lane == 31) wA[warp] = pv;

    unsigned int sv = encS;
#pragma unroll
    for (int o = 1; o < 32; o <<= 1) {
        unsigned int n = __shfl_down_sync(0xffffffffu, sv, o);
        if (lane + o < 32) sv = max(sv, n);
    }
    if (lane == 0) wS[warp] = sv;
    __syncthreads();

    unsigned int offA = 0u, offS = 0u;
    for (int w = 0; w < warp; ++w)     offA = max(offA, wA[w]);
    for (int w = warp + 1; w < 8; ++w) offS = max(offS, wS[w]);
    pv = max(pv, offA);
    sv = max(sv, offS);

    float c   = sC[tid];
    float dLo = pv ? (c - __uint_as_float(pv - 1u)) : FLT_MAX;
    float dHi = sv ? (__uint_as_float(~sv) - c)     : FLT_MAX;
    float d   = fminf(dLo, dHi);

#pragma unroll
    for (int o = 16; o >= 1; o >>= 1) d += __shfl_down_sync(0xffffffffu, d, o);
    if (lane == 0) wsum[warp] = d;
    __syncthreads();

    if (tid == 0) {
        float s = 0.0f;
        for (int w = 0; w < 8; ++w) s += wsum[w];
        g_batchSum[b] = s;

        unsigned int old = atom_add_acqrel(&g_done, 1u);
        if (old == (unsigned)(B - 1)) {
            float tot = 0.0f;
            for (int j = 0; j < B; ++j) tot += g_batchSum[j];
            out[0] = tot;
            g_done = 0u;   // reset for next replay
        }
    }
}

extern "C" void kernel_launch(void* const* d_in, const int* in_sizes, int n_in,
                              void* d_out, int out_size)
{
    int bi = 0, di = 1;
    if (n_in >= 2 && in_sizes[0] > in_sizes[1]) { bi = 1; di = 0; }
    const float* bins  = (const float*)d_in[bi];
    const float* depth = (const float*)d_in[di];

    const int B = in_sizes[bi] / (P_BINS + 1);
    const int M = in_sizes[di] / B;

    const int M4 = M >> 2;
    const int splits = (M4 + TPB - 1) / TPB;   // 75 for 320x240: one float4/thread

    k_prep<<<B, P_BINS>>>(bins);
    dim3 grid(splits, B);
    k_main<<<grid, TPB>>>(depth, M, B, (float*)d_out);
}